// round 4
// baseline (speedup 1.0000x reference)
#include <cuda_runtime.h>
#include <cstdint>
#include <math_constants.h>

#define B      128
#define HH     400
#define WW     400
#define HW     160000
#define WPR    13            // 32-bit words per row
#define NWORDS 5200          // 400 * 13
#define NA     2500
#define NP     20000
#define NI     (HW - NP)
#define CAND_CAP 16384
#define CPB    10            // chunks (CTAs) per batch for streaming passes
#define CHUNK  (HW / CPB)    // 16000 elements
#define CH4    (CHUNK / 4)   // 4000 float4

// Output layout: flat f32 concat of (out_idx, query_pos, new_mask, xy_vox_idx, ignore_idx)
#define OI_OFF 0l
#define QP_OFF 2560000l
#define NM_OFF 33280000l
#define XY_OFF 53760000l
#define IG_OFF 58880000l

__device__ uint32_t g_keys[(size_t)B * HW];      // 81.9 MB
__device__ uint32_t g_hist[B * 2048];
__device__ int      g_cnt[B];
__device__ uint2    g_pivot[B];                  // {p1, rem}
__device__ uint32_t g_candk[B][CAND_CAP];
__device__ uint32_t g_candi[B][CAND_CAP];
__device__ uint32_t g_anchor[B * NWORDS];
__device__ uint32_t g_dil[B * NWORDS];
__device__ int      g_prefix[B * NWORDS];
__device__ int      g_total[B];

// Monotone bijection float -> uint32 (ascending)
__device__ __forceinline__ uint32_t mono_key(float v) {
    uint32_t u = __float_as_uint(v);
    return (u & 0x80000000u) ? ~u : (u | 0x80000000u);
}

// Key for score = sigmoid(p) * m, in logit comparison domain.
__device__ __forceinline__ uint32_t score_key(float p, float m) {
    if (m == 1.0f) return mono_key(p);
    if (m == 0.0f) return mono_key(-CUDART_INF_F);
    float s = __fdividef(1.0f, 1.0f + __expf(-p)) * m;
    float pe;
    if (s <= 0.0f)      pe = -CUDART_INF_F;
    else if (s >= 1.0f) pe =  CUDART_INF_F;
    else                pe = __logf(s) - __logf(1.0f - s);
    return mono_key(pe);
}

// ---------------------------------------------------------------------------
// K0: zero scratch (g_hist, g_cnt, g_anchor)
// ---------------------------------------------------------------------------
__global__ void k_zero()
{
    int t = blockIdx.x * blockDim.x + threadIdx.x;
    int stride = gridDim.x * blockDim.x;
    for (int i = t; i < B * 2048; i += stride) g_hist[i] = 0;
    for (int i = t; i < B * NWORDS; i += stride) g_anchor[i] = 0;
    if (t < B) g_cnt[t] = 0;
}

// ---------------------------------------------------------------------------
// K1: keygen + per-CTA privatized 2048-bin histogram -> global per-batch hist
// grid (CPB, B) x 256
// ---------------------------------------------------------------------------
__global__ __launch_bounds__(256) void k_hist(const float* __restrict__ pred,
                                              const float* __restrict__ mask)
{
    __shared__ uint32_t hist[2048];
    const int b = blockIdx.y, chunk = blockIdx.x, tid = threadIdx.x, lane = tid & 31;
    for (int i = tid; i < 2048; i += 256) hist[i] = 0;
    __syncthreads();

    const float4* p4 = (const float4*)(pred + (size_t)b * HW) + chunk * CH4;
    const float4* m4 = (const float4*)(mask + (size_t)b * HW) + chunk * CH4;
    uint4*        k4 = (uint4*)(g_keys + (size_t)b * HW) + chunk * CH4;

    for (int vb = 0; vb < CH4; vb += 256) {
        int v = vb + tid;
        bool valid = v < CH4;
        uint32_t kk[4] = {0, 0, 0, 0};
        if (valid) {
            float4 pv = __ldcs(&p4[v]);
            float4 mv = __ldcs(&m4[v]);
            kk[0] = score_key(pv.x, mv.x);
            kk[1] = score_key(pv.y, mv.y);
            kk[2] = score_key(pv.z, mv.z);
            kk[3] = score_key(pv.w, mv.w);
            k4[v] = make_uint4(kk[0], kk[1], kk[2], kk[3]);
        }
        #pragma unroll
        for (int j = 0; j < 4; j++) {
            uint32_t bin = kk[j] >> 21;
            unsigned act = __ballot_sync(0xffffffffu, valid);
            if (valid) {
                unsigned peers = __match_any_sync(act, bin);
                if ((unsigned)lane == (unsigned)(__ffs(peers) - 1))
                    atomicAdd(&hist[bin], __popc(peers));
            }
        }
    }
    __syncthreads();
    for (int i = tid; i < 2048; i += 256)
        if (hist[i]) atomicAdd(&g_hist[b * 2048 + i], hist[i]);
}

// suffix-scan select on smem hist: largest digit d with sum_{d'>=d} >= rem.
// blockDim must be 1024.
__device__ __forceinline__ void suffix_select(uint32_t* hist, int nbins, uint32_t remv,
                                              uint32_t* s_dig, uint32_t* s_rem)
{
    const int tid = threadIdx.x;
    for (int off = 1; off < nbins; off <<= 1) {
        int d0 = tid, d1 = tid + 1024;
        uint32_t v0 = 0, v1 = 0;
        if (d0 < nbins && d0 + off < nbins) v0 = hist[d0 + off];
        if (d1 < nbins && d1 + off < nbins) v1 = hist[d1 + off];
        __syncthreads();
        if (d0 < nbins) hist[d0] += v0;
        if (d1 < nbins) hist[d1] += v1;
        __syncthreads();
    }
    int d0 = tid, d1 = tid + 1024;
    if (d0 < nbins) {
        uint32_t ge = hist[d0], gt = (d0 + 1 < nbins) ? hist[d0 + 1] : 0u;
        if (ge >= remv && gt < remv) { *s_dig = (uint32_t)d0; *s_rem = remv - gt; }
    }
    if (d1 < nbins) {
        uint32_t ge = hist[d1], gt = (d1 + 1 < nbins) ? hist[d1 + 1] : 0u;
        if (ge >= remv && gt < remv) { *s_dig = (uint32_t)d1; *s_rem = remv - gt; }
    }
    __syncthreads();
}

// ---------------------------------------------------------------------------
// K2: find first-round pivot per batch. grid B x 1024.
// ---------------------------------------------------------------------------
__global__ __launch_bounds__(1024) void k_pivot()
{
    __shared__ uint32_t hist[2048];
    __shared__ uint32_t s_dig, s_rem;
    const int b = blockIdx.x, tid = threadIdx.x;
    hist[tid] = g_hist[b * 2048 + tid];
    hist[tid + 1024] = g_hist[b * 2048 + tid + 1024];
    __syncthreads();
    suffix_select(hist, 2048, NA, &s_dig, &s_rem);
    if (tid == 0) g_pivot[b] = make_uint2(s_dig, s_rem);
}

// ---------------------------------------------------------------------------
// K3: mark digit>p1 anchors; compact digit==p1 candidates. grid (CPB, B) x 256
// ---------------------------------------------------------------------------
__global__ __launch_bounds__(256) void k_mark()
{
    const int b = blockIdx.y, chunk = blockIdx.x, tid = threadIdx.x, lane = tid & 31;
    const uint32_t p1 = g_pivot[b].x;
    const uint4* k4 = (const uint4*)(g_keys + (size_t)b * HW) + chunk * CH4;
    const int ibase = chunk * CHUNK;

    for (int vb = 0; vb < CH4; vb += 256) {
        int v = vb + tid;
        bool valid = v < CH4;
        uint4 kv = valid ? __ldcs(&k4[v]) : make_uint4(0, 0, 0, 0);
        uint32_t kk[4] = {kv.x, kv.y, kv.z, kv.w};
        #pragma unroll
        for (int j = 0; j < 4; j++) {
            uint32_t d = kk[j] >> 21;
            int i = ibase + v * 4 + j;
            if (valid && d > p1) {
                int r = i / WW, c = i - r * WW;
                atomicOr(&g_anchor[b * NWORDS + r * WPR + (c >> 5)], 1u << (c & 31));
            }
            bool cand = valid && (d == p1);
            unsigned bal = __ballot_sync(0xffffffffu, cand);
            if (bal) {
                int leader = __ffs(bal) - 1;
                int basep = 0;
                if (lane == leader) basep = atomicAdd(&g_cnt[b], __popc(bal));
                basep = __shfl_sync(0xffffffffu, basep, leader);
                if (cand) {
                    int off = basep + __popc(bal & ((1u << lane) - 1u));
                    if (off < CAND_CAP) { g_candk[b][off] = kk[j]; g_candi[b][off] = (uint32_t)i; }
                }
            }
        }
    }
}

// ---------------------------------------------------------------------------
// K4: per-batch finisher — radix rounds 2&3 on candidates, tie resolve,
//     dilation, popcount prefix. grid B x 1024. hist unioned with hd.
// ---------------------------------------------------------------------------
__global__ __launch_bounds__(1024) void k_finish()
{
    __shared__ uint32_t sbm[NWORDS];
    __shared__ uint32_t hd[NWORDS];       // doubles as hist[0..2047]
    __shared__ uint32_t s_dig, s_rem;
    __shared__ int swarp[32];
    __shared__ int s_tot;
    uint32_t* hist = hd;

    const int b = blockIdx.x, tid = threadIdx.x, lane = tid & 31, wid = tid >> 5;
    const uint32_t p1 = g_pivot[b].x;
    uint32_t rem = g_pivot[b].y;
    const int nc = min(g_cnt[b], CAND_CAP);

    for (int w = tid; w < NWORDS; w += 1024) sbm[w] = g_anchor[b * NWORDS + w];
    for (int i = tid; i < 2048; i += 1024) hist[i] = 0;
    __syncthreads();

    // round 2: bits [10:21)
    for (int j = tid; j < nc; j += 1024) atomicAdd(&hist[(g_candk[b][j] >> 10) & 2047u], 1u);
    __syncthreads();
    suffix_select(hist, 2048, rem, &s_dig, &s_rem);
    const uint32_t d2 = s_dig; rem = s_rem;
    __syncthreads();

    // round 3: bits [0:10)
    hist[tid] = 0;
    __syncthreads();
    for (int j = tid; j < nc; j += 1024) {
        uint32_t k = g_candk[b][j];
        if (((k >> 10) & 2047u) == d2) atomicAdd(&hist[k & 1023u], 1u);
    }
    __syncthreads();
    suffix_select(hist, 1024, rem, &s_dig, &s_rem);
    const uint32_t K = (p1 << 21) | (d2 << 10) | s_dig;
    const uint32_t T = s_rem;
    __syncthreads();

    // mark candidate anchors (stable tie-break by ascending index)
    for (int j = tid; j < nc; j += 1024) {
        uint32_t k = g_candk[b][j];
        bool anc = false;
        if (k > K) anc = true;
        else if (k == K) {
            uint32_t myi = g_candi[b][j], rank = 0;
            for (int t = 0; t < nc; t++)
                if (g_candk[b][t] == K && g_candi[b][t] < myi) rank++;
            if (rank < T) anc = true;
        }
        if (anc) {
            int i = (int)g_candi[b][j];
            int r = i / WW, c = i - r * WW;
            atomicOr(&sbm[r * WPR + (c >> 5)], 1u << (c & 31));
        }
    }
    __syncthreads();

    // 5x5 dilation
    for (int w = tid; w < NWORDS; w += 1024) {
        int wi = w % WPR;
        uint32_t c    = sbm[w];
        uint32_t prev = (wi > 0)       ? sbm[w - 1] : 0u;
        uint32_t next = (wi < WPR - 1) ? sbm[w + 1] : 0u;
        uint32_t h = c | (c << 1) | (c << 2) | (c >> 1) | (c >> 2)
                   | (prev >> 31) | (prev >> 30) | (next << 31) | (next << 30);
        if (wi == WPR - 1) h &= 0xFFFFu;
        hd[w] = h;
    }
    __syncthreads();
    for (int w = tid; w < NWORDS; w += 1024) {
        int r = w / WPR;
        uint32_t vv = hd[w];
        if (r >= 1)   vv |= hd[w - WPR];
        if (r >= 2)   vv |= hd[w - 2 * WPR];
        if (r <= 398) vv |= hd[w + WPR];
        if (r <= 397) vv |= hd[w + 2 * WPR];
        sbm[w] = vv;
        g_dil[b * NWORDS + w] = vv;
    }
    __syncthreads();

    // exclusive prefix of popcounts
    int running = 0;
    for (int base = 0; base < NWORDS; base += 1024) {
        int w = base + tid;
        int c = (w < NWORDS) ? __popc(sbm[w]) : 0;
        int v = c;
        for (int o = 1; o < 32; o <<= 1) { int n = __shfl_up_sync(0xffffffffu, v, o); if (lane >= o) v += n; }
        if (lane == 31) swarp[wid] = v;
        __syncthreads();
        if (wid == 0) {
            int t = swarp[lane], tv = t;
            for (int o = 1; o < 32; o <<= 1) { int n = __shfl_up_sync(0xffffffffu, tv, o); if (lane >= o) tv += n; }
            swarp[lane] = tv - t;
            if (lane == 31) s_tot = tv;
        }
        __syncthreads();
        if (w < NWORDS) g_prefix[b * NWORDS + w] = running + swarp[wid] + (v - c);
        running += s_tot;
        __syncthreads();
    }
    if (tid == 0) g_total[b] = running;
}

// ---------------------------------------------------------------------------
// k_write: one thread per element; streaming stores for all outputs.
// ---------------------------------------------------------------------------
__global__ __launch_bounds__(256) void k_write(const float* __restrict__ grid,
                                               const float* __restrict__ zs,
                                               float* __restrict__ out)
{
    const int b = blockIdx.y;
    const int i = blockIdx.x * 256 + threadIdx.x;
    if (i >= HW) return;

    const int r  = i / WW;
    const int c  = i - r * WW;
    const int w  = r * WPR + (c >> 5);
    const int bi = c & 31;

    const uint32_t bits = __ldg(&g_dil[b * NWORDS + w]);
    const int pre       = __ldg(&g_prefix[b * NWORDS + w]);
    const int S         = g_total[b];

    const bool set     = (bits >> bi) & 1u;
    const int  setrank = pre + __popc(bits & ((1u << bi) - 1u));
    const int  pos     = set ? setrank : S + (i - setrank);

    __stcs(&out[NM_OFF + (size_t)b * HW + i], (pos < NP) ? 1.0f : 0.0f);

    if (pos < NP) {
        __stcs(&out[OI_OFF + (size_t)b * NP + pos], (float)i);
        size_t xb = XY_OFF + ((size_t)b * NP + pos) * 2;
        __stcs(&out[xb],     (float)r);
        __stcs(&out[xb + 1], (float)c);
        float gx = __ldg(&grid[2 * i]), gy = __ldg(&grid[2 * i + 1]);
        float z0 = __ldg(&zs[0]), z1 = __ldg(&zs[1]), z2 = __ldg(&zs[2]), z3 = __ldg(&zs[3]);
        size_t qb = QP_OFF + (size_t)b * 240000 + (size_t)pos * 3;
        __stcs(&out[qb],          gx); __stcs(&out[qb + 1],      gy); __stcs(&out[qb + 2],      z0);
        __stcs(&out[qb + 60000],  gx); __stcs(&out[qb + 60001],  gy); __stcs(&out[qb + 60002],  z1);
        __stcs(&out[qb + 120000], gx); __stcs(&out[qb + 120001], gy); __stcs(&out[qb + 120002], z2);
        __stcs(&out[qb + 180000], gx); __stcs(&out[qb + 180001], gy); __stcs(&out[qb + 180002], z3);
    } else {
        __stcs(&out[IG_OFF + (size_t)b * NI + (pos - NP)], (float)i);
    }
}

// ---------------------------------------------------------------------------
extern "C" void kernel_launch(void* const* d_in, const int* in_sizes, int n_in,
                              void* d_out, int out_size)
{
    const float* pred = nullptr;
    const float* mask = nullptr;
    const float* grid = nullptr;
    const float* zs   = nullptr;
    for (int i = 0; i < n_in; i++) {
        if (in_sizes[i] == B * HW) {
            if (!pred) pred = (const float*)d_in[i];
            else if (!mask) mask = (const float*)d_in[i];
        } else if (in_sizes[i] == HW * 2) {
            grid = (const float*)d_in[i];
        } else if (in_sizes[i] == 4) {
            zs = (const float*)d_in[i];
        }
    }
    float* out = (float*)d_out;

    k_zero<<<256, 256>>>();
    dim3 gs(CPB, B);
    k_hist<<<gs, 256>>>(pred, mask);
    k_pivot<<<B, 1024>>>();
    k_mark<<<gs, 256>>>();
    k_finish<<<B, 1024>>>();
    dim3 gw((HW + 255) / 256, B);
    k_write<<<gw, 256>>>(grid, zs, out);
}

// round 5
// speedup vs baseline: 1.3095x; 1.3095x over previous
#include <cuda_runtime.h>
#include <cstdint>
#include <math_constants.h>

#define B      128
#define HH     400
#define WW     400
#define HW     160000
#define WPR    13            // 32-bit words per row
#define NWORDS 5200          // 400 * 13
#define NA     2500
#define NP     20000
#define NI     (HW - NP)
#define CAND_CAP 16384

// Output layout: flat f32 concat of (out_idx, query_pos, new_mask, xy_vox_idx, ignore_idx)
#define OI_OFF 0l
#define QP_OFF 2560000l
#define NM_OFF 33280000l
#define XY_OFF 53760000l
#define IG_OFF 58880000l

__device__ uint32_t g_keys16[(size_t)B * HW / 2];   // packed 16-bit keys, 41 MB
__device__ uint32_t g_dil[B * NWORDS];
__device__ int      g_prefix[B * NWORDS];
__device__ int      g_total[B];

// Monotone bijection float -> uint32 (ascending)
__device__ __forceinline__ uint32_t mono_key(float v) {
    uint32_t u = __float_as_uint(v);
    return (u & 0x80000000u) ? ~u : (u | 0x80000000u);
}

// Key for score = sigmoid(p) * m, in logit comparison domain.
__device__ __forceinline__ uint32_t score_key(float p, float m) {
    if (m == 1.0f) return mono_key(p);
    if (m == 0.0f) return mono_key(-CUDART_INF_F);
    float s = __fdividef(1.0f, 1.0f + __expf(-p)) * m;
    float pe;
    if (s <= 0.0f)      pe = -CUDART_INF_F;
    else if (s >= 1.0f) pe =  CUDART_INF_F;
    else                pe = __logf(s) - __logf(1.0f - s);
    return mono_key(pe);
}

// ---------------------------------------------------------------------------
// Fused per-batch kernel: top-2500 radix select + 5x5 dilation + prefix.
// One 1024-thread CTA per batch. Dynamic smem:
//   hist[2048] | sbm[NWORDS] | hd[NWORDS] | candk[CAND_CAP] | candi[CAND_CAP]
// ---------------------------------------------------------------------------
#define SMEM_BYTES ((2048 + NWORDS + NWORDS + CAND_CAP + CAND_CAP) * 4)

__global__ __launch_bounds__(1024) void k_select_dilate(const float* __restrict__ pred,
                                                        const float* __restrict__ mask)
{
    extern __shared__ uint32_t smem[];
    uint32_t* hist  = smem;
    uint32_t* sbm   = hist + 2048;
    uint32_t* hd    = sbm + NWORDS;
    uint32_t* candk = hd + NWORDS;
    uint32_t* candi = candk + CAND_CAP;

    __shared__ uint32_t s_dig, s_rem;
    __shared__ int      s_ncand;
    __shared__ int      swarp[32];
    __shared__ int      s_tot;

    const int b = blockIdx.x, tid = threadIdx.x, lane = tid & 31, wid = tid >> 5;
    const float* pb = pred + (size_t)b * HW;
    const float* mb = mask + (size_t)b * HW;
    uint2*       k16 = (uint2*)(g_keys16 + (size_t)b * HW / 2);

    for (int i = tid; i < 2048;   i += 1024) hist[i] = 0;
    for (int i = tid; i < NWORDS; i += 1024) sbm[i]  = 0;
    if (tid == 0) s_ncand = 0;
    __syncthreads();

    // ---- Pass 1: keygen + 11-bit histogram; store only top-16 key bits.
    {
        const float4* p4 = (const float4*)pb;
        const float4* m4 = (const float4*)mb;
        for (int v = tid; v < HW / 4; v += 1024) {
            float4 pv = p4[v], mv = m4[v];
            uint32_t k0 = score_key(pv.x, mv.x);
            uint32_t k1 = score_key(pv.y, mv.y);
            uint32_t k2 = score_key(pv.z, mv.z);
            uint32_t k3 = score_key(pv.w, mv.w);
            uint2 pk;
            pk.x = (k0 >> 16) | (k1 & 0xFFFF0000u);
            pk.y = (k2 >> 16) | (k3 & 0xFFFF0000u);
            k16[v] = pk;
            uint32_t kk[4] = {k0, k1, k2, k3};
            #pragma unroll
            for (int j = 0; j < 4; j++) {
                uint32_t bin = kk[j] >> 21;
                unsigned peers = __match_any_sync(0xffffffffu, bin);
                if ((unsigned)lane == (unsigned)(__ffs(peers) - 1))
                    atomicAdd(&hist[bin], __popc(peers));
            }
        }
    }
    __syncthreads();

    // suffix-scan select: largest digit d with sum_{d'>=d} hist[d'] >= rem
    auto suffix_select = [&](int nbins, uint32_t remv) {
        for (int off = 1; off < nbins; off <<= 1) {
            int d0 = tid, d1 = tid + 1024;
            uint32_t v0 = 0, v1 = 0;
            if (d0 < nbins && d0 + off < nbins) v0 = hist[d0 + off];
            if (d1 < nbins && d1 + off < nbins) v1 = hist[d1 + off];
            __syncthreads();
            if (d0 < nbins) hist[d0] += v0;
            if (d1 < nbins) hist[d1] += v1;
            __syncthreads();
        }
        int d0 = tid, d1 = tid + 1024;
        if (d0 < nbins) {
            uint32_t ge = hist[d0], gt = (d0 + 1 < nbins) ? hist[d0 + 1] : 0u;
            if (ge >= remv && gt < remv) { s_dig = (uint32_t)d0; s_rem = remv - gt; }
        }
        if (d1 < nbins) {
            uint32_t ge = hist[d1], gt = (d1 + 1 < nbins) ? hist[d1 + 1] : 0u;
            if (ge >= remv && gt < remv) { s_dig = (uint32_t)d1; s_rem = remv - gt; }
        }
        __syncthreads();
    };

    uint32_t rem = NA;
    suffix_select(2048, rem);
    const uint32_t p1 = s_dig; rem = s_rem;
    __syncthreads();

    // ---- Pass 2: classify from 16-bit keys (L2-resident). digit = k16 >> 5.
    {
        for (int v = tid; v < HW / 4; v += 1024) {
            uint2 pk = k16[v];
            uint32_t ss[4] = { pk.x & 0xFFFFu, pk.x >> 16, pk.y & 0xFFFFu, pk.y >> 16 };
            #pragma unroll
            for (int j = 0; j < 4; j++) {
                uint32_t d = ss[j] >> 5;
                int i = v * 4 + j;
                if (d > p1) {
                    int r = i / WW, c = i - r * WW;
                    atomicOr(&sbm[r * WPR + (c >> 5)], 1u << (c & 31));
                } else if (d == p1) {
                    int slot = atomicAdd(&s_ncand, 1);
                    if (slot < CAND_CAP) candi[slot] = (uint32_t)i;
                }
            }
        }
    }
    __syncthreads();
    const int nc = min(s_ncand, CAND_CAP);

    // Recompute full 32-bit keys for candidates (gathers; L2 hits)
    for (int j = tid; j < nc; j += 1024) {
        int i = (int)candi[j];
        candk[j] = score_key(pb[i], mb[i]);
    }
    __syncthreads();

    // ---- Candidate round 2: bits [10:21)
    for (int i = tid; i < 2048; i += 1024) hist[i] = 0;
    __syncthreads();
    for (int j = tid; j < nc; j += 1024) atomicAdd(&hist[(candk[j] >> 10) & 2047u], 1u);
    __syncthreads();
    suffix_select(2048, rem);
    const uint32_t d2 = s_dig; rem = s_rem;
    __syncthreads();

    // ---- Candidate round 3: bits [0:10)
    hist[tid] = 0;
    __syncthreads();
    for (int j = tid; j < nc; j += 1024) {
        uint32_t k = candk[j];
        if (((k >> 10) & 2047u) == d2) atomicAdd(&hist[k & 1023u], 1u);
    }
    __syncthreads();
    suffix_select(1024, rem);
    const uint32_t K = (p1 << 21) | (d2 << 10) | s_dig;
    const uint32_t T = s_rem;     // ties at K to take, ascending index order
    __syncthreads();

    // ---- Mark candidate anchors (stable tie-break by ascending index)
    for (int j = tid; j < nc; j += 1024) {
        uint32_t k = candk[j];
        bool anc = false;
        if (k > K) anc = true;
        else if (k == K) {
            uint32_t myi = candi[j], rank = 0;
            for (int t = 0; t < nc; t++)
                if (candk[t] == K && candi[t] < myi) rank++;
            if (rank < T) anc = true;
        }
        if (anc) {
            int i = (int)candi[j];
            int r = i / WW, c = i - r * WW;
            atomicOr(&sbm[r * WPR + (c >> 5)], 1u << (c & 31));
        }
    }
    __syncthreads();

    // ---- 5x5 dilation via bitwise shifts
    for (int w = tid; w < NWORDS; w += 1024) {
        int wi = w % WPR;
        uint32_t c    = sbm[w];
        uint32_t prev = (wi > 0)       ? sbm[w - 1] : 0u;
        uint32_t next = (wi < WPR - 1) ? sbm[w + 1] : 0u;
        uint32_t h = c | (c << 1) | (c << 2) | (c >> 1) | (c >> 2)
                   | (prev >> 31) | (prev >> 30) | (next << 31) | (next << 30);
        if (wi == WPR - 1) h &= 0xFFFFu;
        hd[w] = h;
    }
    __syncthreads();
    for (int w = tid; w < NWORDS; w += 1024) {
        int r = w / WPR;
        uint32_t vv = hd[w];
        if (r >= 1)   vv |= hd[w - WPR];
        if (r >= 2)   vv |= hd[w - 2 * WPR];
        if (r <= 398) vv |= hd[w + WPR];
        if (r <= 397) vv |= hd[w + 2 * WPR];
        sbm[w] = vv;                        // sbm now holds dilated bitmap
        g_dil[b * NWORDS + w] = vv;
    }
    __syncthreads();

    // ---- Exclusive prefix of word popcounts
    int running = 0;
    for (int base = 0; base < NWORDS; base += 1024) {
        int w = base + tid;
        int c = (w < NWORDS) ? __popc(sbm[w]) : 0;
        int v = c;
        for (int o = 1; o < 32; o <<= 1) { int n = __shfl_up_sync(0xffffffffu, v, o); if (lane >= o) v += n; }
        if (lane == 31) swarp[wid] = v;
        __syncthreads();
        if (wid == 0) {
            int t = swarp[lane], tv = t;
            for (int o = 1; o < 32; o <<= 1) { int n = __shfl_up_sync(0xffffffffu, tv, o); if (lane >= o) tv += n; }
            swarp[lane] = tv - t;
            if (lane == 31) s_tot = tv;
        }
        __syncthreads();
        if (w < NWORDS) g_prefix[b * NWORDS + w] = running + swarp[wid] + (v - c);
        running += s_tot;
        __syncthreads();
    }
    if (tid == 0) g_total[b] = running;
}

// ---------------------------------------------------------------------------
// k_write: one thread per element; streaming stores for all outputs.
// pos(i) = setrank(i) if set else S + (i - setrank(i))
// ---------------------------------------------------------------------------
__global__ __launch_bounds__(256) void k_write(const float* __restrict__ grid,
                                               const float* __restrict__ zs,
                                               float* __restrict__ out)
{
    const int b = blockIdx.y;
    const int i = blockIdx.x * 256 + threadIdx.x;
    if (i >= HW) return;

    const int r  = i / WW;
    const int c  = i - r * WW;
    const int w  = r * WPR + (c >> 5);
    const int bi = c & 31;

    const uint32_t bits = __ldg(&g_dil[b * NWORDS + w]);
    const int pre       = __ldg(&g_prefix[b * NWORDS + w]);
    const int S         = g_total[b];

    const bool set     = (bits >> bi) & 1u;
    const int  setrank = pre + __popc(bits & ((1u << bi) - 1u));
    const int  pos     = set ? setrank : S + (i - setrank);

    __stcs(&out[NM_OFF + (size_t)b * HW + i], (pos < NP) ? 1.0f : 0.0f);

    if (pos < NP) {
        __stcs(&out[OI_OFF + (size_t)b * NP + pos], (float)i);
        size_t xb = XY_OFF + ((size_t)b * NP + pos) * 2;
        __stcs(&out[xb],     (float)r);
        __stcs(&out[xb + 1], (float)c);
        float gx = __ldg(&grid[2 * i]), gy = __ldg(&grid[2 * i + 1]);
        float z0 = __ldg(&zs[0]), z1 = __ldg(&zs[1]), z2 = __ldg(&zs[2]), z3 = __ldg(&zs[3]);
        size_t qb = QP_OFF + (size_t)b * 240000 + (size_t)pos * 3;
        __stcs(&out[qb],          gx); __stcs(&out[qb + 1],      gy); __stcs(&out[qb + 2],      z0);
        __stcs(&out[qb + 60000],  gx); __stcs(&out[qb + 60001],  gy); __stcs(&out[qb + 60002],  z1);
        __stcs(&out[qb + 120000], gx); __stcs(&out[qb + 120001], gy); __stcs(&out[qb + 120002], z2);
        __stcs(&out[qb + 180000], gx); __stcs(&out[qb + 180001], gy); __stcs(&out[qb + 180002], z3);
    } else {
        __stcs(&out[IG_OFF + (size_t)b * NI + (pos - NP)], (float)i);
    }
}

// ---------------------------------------------------------------------------
extern "C" void kernel_launch(void* const* d_in, const int* in_sizes, int n_in,
                              void* d_out, int out_size)
{
    const float* pred = nullptr;
    const float* mask = nullptr;
    const float* grid = nullptr;
    const float* zs   = nullptr;
    for (int i = 0; i < n_in; i++) {
        if (in_sizes[i] == B * HW) {
            if (!pred) pred = (const float*)d_in[i];
            else if (!mask) mask = (const float*)d_in[i];
        } else if (in_sizes[i] == HW * 2) {
            grid = (const float*)d_in[i];
        } else if (in_sizes[i] == 4) {
            zs = (const float*)d_in[i];
        }
    }
    float* out = (float*)d_out;

    cudaFuncSetAttribute(k_select_dilate, cudaFuncAttributeMaxDynamicSharedMemorySize, SMEM_BYTES);

    k_select_dilate<<<B, 1024, SMEM_BYTES>>>(pred, mask);
    dim3 gw((HW + 255) / 256, B);
    k_write<<<gw, 256>>>(grid, zs, out);
}